// round 1
// baseline (speedup 1.0000x reference)
#include <cuda_runtime.h>
#include <cuda_bf16.h>
#include <cstdint>

#define NN 200000
#define NF 400000
#define NE (3*NF)

#define BM 128
#define BN 256
#define BK 32
#define KTOT 512   // W2 split into hi+lo bf16 halves for precision

// ---------------- scratch (static device globals; no runtime allocation) ----
__device__ int g_deg[NN];
__device__ int g_rowptr[NN + 1];
__device__ int g_cursor[NN];
__device__ int g_bsums[256];
__device__ int g_colidx[NE];
__device__ __nv_bfloat16 g_h1[(size_t)NN * 256];   // 102.4 MB
__device__ float g_tu[(size_t)NN * 256];           // 204.8 MB: cols 0..127 = t, 128..255 = u
__device__ __nv_bfloat16 g_Wc[KTOT * 256];         // [512][256]: rows 0-255 hi(W2l|W2r), 256-511 lo residual
__device__ float g_gsum[128];

// ---------------- K0: zero counters ----------------------------------------
__global__ void k_zero() {
    int i = blockIdx.x * blockDim.x + threadIdx.x;
    if (i < NN) g_deg[i] = 0;
    if (i < 128) g_gsum[i] = 0.0f;
}

// ---------------- Kw: build combined split-precision weight matrix ---------
__global__ void k_weights(const float* __restrict__ W2l, const float* __restrict__ W2r) {
    int idx = blockIdx.x * blockDim.x + threadIdx.x;
    if (idx >= KTOT * 256) return;
    int k = idx >> 8, c = idx & 255;
    int ks = k & 255;
    float w = (c < 128) ? W2l[ks * 128 + c] : W2r[ks * 128 + (c - 128)];
    __nv_bfloat16 hi = __float2bfloat16(w);
    if (k < 256) g_Wc[idx] = hi;
    else         g_Wc[idx] = __float2bfloat16(w - __bfloat162float(hi));
}

// ---------------- edge decode helper ----------------------------------------
__device__ __forceinline__ void edge_decode(const int* __restrict__ face, int e,
                                            int& src, int& dst) {
    int t = e / NF;
    int f = e - t * NF;
    if (t == 0)      { src = face[f];          dst = face[NF + f];     }
    else if (t == 1) { src = face[NF + f];     dst = face[2 * NF + f]; }
    else             { src = face[f];          dst = face[2 * NF + f]; }
}

// ---------------- K1: degree histogram --------------------------------------
__global__ void k_hist(const int* __restrict__ face) {
    int e = blockIdx.x * blockDim.x + threadIdx.x;
    if (e >= NE) return;
    int src, dst;
    edge_decode(face, e, src, dst);
    if (src != dst) atomicAdd(&g_deg[dst], 1);
}

// ---------------- scan (3 kernels) ------------------------------------------
__global__ void k_scan1() {
    __shared__ int s[1024];
    int i = blockIdx.x * 1024 + threadIdx.x;
    int v = (i < NN) ? g_deg[i] : 0;
    s[threadIdx.x] = v;
    __syncthreads();
    #pragma unroll
    for (int off = 1; off < 1024; off <<= 1) {
        int t = (threadIdx.x >= off) ? s[threadIdx.x - off] : 0;
        __syncthreads();
        s[threadIdx.x] += t;
        __syncthreads();
    }
    if (i < NN) g_rowptr[i] = s[threadIdx.x] - v;   // exclusive (local)
    if (threadIdx.x == 1023) g_bsums[blockIdx.x] = s[1023];
}

__global__ void k_scan2() {
    __shared__ int s[256];
    int v = (threadIdx.x < 196) ? g_bsums[threadIdx.x] : 0;
    s[threadIdx.x] = v;
    __syncthreads();
    #pragma unroll
    for (int off = 1; off < 256; off <<= 1) {
        int t = (threadIdx.x >= off) ? s[threadIdx.x - off] : 0;
        __syncthreads();
        s[threadIdx.x] += t;
        __syncthreads();
    }
    g_bsums[threadIdx.x] = s[threadIdx.x] - v;      // exclusive block offsets
    if (threadIdx.x == 255) g_rowptr[NN] = s[255];  // total valid edges
}

__global__ void k_scan3() {
    int i = blockIdx.x * 1024 + threadIdx.x;
    if (i < NN) {
        int r = g_rowptr[i] + g_bsums[i >> 10];
        g_rowptr[i] = r;
        g_cursor[i] = r;
    }
}

// ---------------- Kf: fill CSR column indices --------------------------------
__global__ void k_fill(const int* __restrict__ face) {
    int e = blockIdx.x * blockDim.x + threadIdx.x;
    if (e >= NE) return;
    int src, dst;
    edge_decode(face, e, src, dst);
    if (src != dst) {
        int p = atomicAdd(&g_cursor[dst], 1);
        g_colidx[p] = src;
    }
}

// ---------------- KA: fused layer-1 (agg + dense + relu) -> h1 bf16 ----------
__global__ void k_layer1(const float* __restrict__ pos, const float* __restrict__ W1l,
                         const float* __restrict__ W1r, const float* __restrict__ b1) {
    __shared__ float sw[1792];  // [0..767] W1l, [768..1535] W1r, [1536..1791] b1
    for (int i = threadIdx.x; i < 1792; i += blockDim.x)
        sw[i] = (i < 768) ? W1l[i] : (i < 1536 ? W1r[i - 768] : b1[i - 1536]);
    __syncthreads();
    const float* wl = sw;
    const float* wr = sw + 768;
    const float* bb = sw + 1536;

    int wid = threadIdx.x >> 5, lane = threadIdx.x & 31;
    int node = blockIdx.x * (blockDim.x >> 5) + wid;
    if (node >= NN) return;

    int beg = g_rowptr[node], end = g_rowptr[node + 1];
    float ax = 0.f, ay = 0.f, az = 0.f;
    for (int j = beg + lane; j < end; j += 32) {
        int s = g_colidx[j];
        ax += pos[3 * s + 0];
        ay += pos[3 * s + 1];
        az += pos[3 * s + 2];
    }
    #pragma unroll
    for (int off = 16; off; off >>= 1) {
        ax += __shfl_down_sync(0xffffffffu, ax, off);
        ay += __shfl_down_sync(0xffffffffu, ay, off);
        az += __shfl_down_sync(0xffffffffu, az, off);
    }
    float inv = 1.0f / fmaxf((float)(end - beg), 1.0f);
    ax = __shfl_sync(0xffffffffu, ax, 0) * inv;
    ay = __shfl_sync(0xffffffffu, ay, 0) * inv;
    az = __shfl_sync(0xffffffffu, az, 0) * inv;

    float px = pos[3 * node + 0], py = pos[3 * node + 1], pz = pos[3 * node + 2];

    int c0 = lane * 8;
    uint4 outv;
    unsigned* po = (unsigned*)&outv;
    #pragma unroll
    for (int t = 0; t < 4; t++) {
        int c = c0 + 2 * t;
        float h0 = bb[c] + ax * wl[c] + ay * wl[256 + c] + az * wl[512 + c]
                         + px * wr[c] + py * wr[256 + c] + pz * wr[512 + c];
        int c1 = c + 1;
        float h1v = bb[c1] + ax * wl[c1] + ay * wl[256 + c1] + az * wl[512 + c1]
                           + px * wr[c1] + py * wr[256 + c1] + pz * wr[512 + c1];
        h0 = fmaxf(h0, 0.0f);
        h1v = fmaxf(h1v, 0.0f);
        __nv_bfloat162 p2 = __floats2bfloat162_rn(h0, h1v);
        po[t] = *(unsigned*)&p2;
    }
    ((uint4*)(g_h1 + (size_t)node * 256))[lane] = outv;
}

// ---------------- KG: bf16 mma GEMM  tu = h1 @ [Whi ; Wlo]  ------------------
__global__ void __launch_bounds__(512, 1) k_gemm() {
    __shared__ __nv_bfloat16 As[BM][BK + 24];  // stride 56 elems = 112B (16B aligned, conflict-free ldmatrix)
    __shared__ __nv_bfloat16 Bs[BK][BN + 8];   // stride 264 elems = 528B (conflict-free)

    int tid = threadIdx.x;
    int warp = tid >> 5, lane = tid & 31;
    int wm = warp & 3, wn = warp >> 2;          // 4 (M) x 4 (N) warps; warp tile 32x64
    int bm = blockIdx.x * BM;

    float c[2][8][4];
    #pragma unroll
    for (int mi = 0; mi < 2; mi++)
        #pragma unroll
        for (int ni = 0; ni < 8; ni++)
            #pragma unroll
            for (int q = 0; q < 4; q++) c[mi][ni][q] = 0.0f;

    for (int k0 = 0; k0 < KTOT; k0 += BK) {
        // load A tile: 128 x 32 bf16 (wraps K at 256 -> hi/lo passes reuse h1)
        {
            int u = tid;
            int row = u >> 2, cq = u & 3;
            int node = bm + row;
            int kc = (k0 + cq * 8) & 255;
            uint4 val = make_uint4(0, 0, 0, 0);
            if (node < NN) val = *(const uint4*)(g_h1 + (size_t)node * 256 + kc);
            *(uint4*)(&As[row][cq * 8]) = val;
        }
        // load B tile: 32 x 256 bf16
        #pragma unroll
        for (int r = 0; r < 2; r++) {
            int u = tid + 512 * r;
            int row = u >> 5, cq = u & 31;
            uint4 val = *(const uint4*)(g_Wc + (size_t)(k0 + row) * 256 + cq * 8);
            *(uint4*)(&Bs[row][cq * 8]) = val;
        }
        __syncthreads();

        #pragma unroll
        for (int kk = 0; kk < BK; kk += 16) {
            uint32_t a[2][4];
            #pragma unroll
            for (int mi = 0; mi < 2; mi++) {
                int r = wm * 32 + mi * 16 + (lane & 7) + 8 * ((lane >> 3) & 1);
                int cc = kk + 8 * (lane >> 4);
                uint32_t addr = (uint32_t)__cvta_generic_to_shared(&As[r][cc]);
                asm volatile("ldmatrix.sync.aligned.m8n8.x4.shared.b16 {%0,%1,%2,%3}, [%4];"
                             : "=r"(a[mi][0]), "=r"(a[mi][1]), "=r"(a[mi][2]), "=r"(a[mi][3])
                             : "r"(addr));
            }
            #pragma unroll
            for (int np = 0; np < 4; np++) {
                int n0 = wn * 64 + np * 16;
                uint32_t b[4];
                int rr = kk + (lane & 7) + 8 * ((lane >> 3) & 1);
                int ncol = n0 + 8 * (lane >> 4);
                uint32_t baddr = (uint32_t)__cvta_generic_to_shared(&Bs[rr][ncol]);
                asm volatile("ldmatrix.sync.aligned.m8n8.x4.trans.shared.b16 {%0,%1,%2,%3}, [%4];"
                             : "=r"(b[0]), "=r"(b[1]), "=r"(b[2]), "=r"(b[3])
                             : "r"(baddr));
                #pragma unroll
                for (int mi = 0; mi < 2; mi++) {
                    #pragma unroll
                    for (int h = 0; h < 2; h++) {
                        int ni = np * 2 + h;
                        asm volatile(
                            "mma.sync.aligned.m16n8k16.row.col.f32.bf16.bf16.f32 "
                            "{%0,%1,%2,%3},{%4,%5,%6,%7},{%8,%9},{%0,%1,%2,%3};"
                            : "+f"(c[mi][ni][0]), "+f"(c[mi][ni][1]),
                              "+f"(c[mi][ni][2]), "+f"(c[mi][ni][3])
                            : "r"(a[mi][0]), "r"(a[mi][1]), "r"(a[mi][2]), "r"(a[mi][3]),
                              "r"(b[2 * h]), "r"(b[2 * h + 1]));
                    }
                }
            }
        }
        __syncthreads();
    }

    // epilogue: fp32 store to g_tu
    int gid = lane >> 2, qid = lane & 3;
    #pragma unroll
    for (int mi = 0; mi < 2; mi++) {
        int r0 = bm + wm * 32 + mi * 16 + gid;
        int r1 = r0 + 8;
        #pragma unroll
        for (int ni = 0; ni < 8; ni++) {
            int col = wn * 64 + ni * 8 + qid * 2;
            if (r0 < NN)
                *(float2*)(g_tu + (size_t)r0 * 256 + col) = make_float2(c[mi][ni][0], c[mi][ni][1]);
            if (r1 < NN)
                *(float2*)(g_tu + (size_t)r1 * 256 + col) = make_float2(c[mi][ni][2], c[mi][ni][3]);
        }
    }
}

// ---------------- KB: fused layer-2 aggregate + relu + global mean partials --
__global__ void k_layer2(const float* __restrict__ b2) {
    __shared__ float gsh[128];
    if (threadIdx.x < 128) gsh[threadIdx.x] = 0.0f;
    __syncthreads();

    int wid = threadIdx.x >> 5, lane = threadIdx.x & 31;
    int gwarp = blockIdx.x * (blockDim.x >> 5) + wid;
    int nwarps = gridDim.x * (blockDim.x >> 5);
    float4 bl = ((const float4*)b2)[lane];

    float a0 = 0.f, a1 = 0.f, a2 = 0.f, a3 = 0.f;
    for (int node = gwarp; node < NN; node += nwarps) {
        int beg = g_rowptr[node], end = g_rowptr[node + 1];
        float s0 = 0.f, s1 = 0.f, s2 = 0.f, s3 = 0.f;
        for (int j = beg; j < end; j++) {
            int src = g_colidx[j];
            float4 tv = ((const float4*)(g_tu + (size_t)src * 256))[lane];
            s0 += tv.x; s1 += tv.y; s2 += tv.z; s3 += tv.w;
        }
        float inv = 1.0f / fmaxf((float)(end - beg), 1.0f);
        float4 uv = ((const float4*)(g_tu + (size_t)node * 256 + 128))[lane];
        a0 += fmaxf(s0 * inv + uv.x + bl.x, 0.0f);
        a1 += fmaxf(s1 * inv + uv.y + bl.y, 0.0f);
        a2 += fmaxf(s2 * inv + uv.z + bl.z, 0.0f);
        a3 += fmaxf(s3 * inv + uv.w + bl.w, 0.0f);
    }
    atomicAdd(&gsh[lane * 4 + 0], a0);
    atomicAdd(&gsh[lane * 4 + 1], a1);
    atomicAdd(&gsh[lane * 4 + 2], a2);
    atomicAdd(&gsh[lane * 4 + 3], a3);
    __syncthreads();
    if (threadIdx.x < 128) atomicAdd(&g_gsum[threadIdx.x], gsh[threadIdx.x]);
}

// ---------------- KC: decoder + softmax + argmax -----------------------------
__global__ void k_final(const float* __restrict__ Wd, const float* __restrict__ bd,
                        float* __restrict__ out, int out_size) {
    if (threadIdx.x != 0 || blockIdx.x != 0) return;
    float g[128];
    for (int c = 0; c < 128; c++) g[c] = g_gsum[c] * (1.0f / (float)NN);
    float lg[10];
    for (int j = 0; j < 10; j++) lg[j] = bd[j];
    for (int c = 0; c < 128; c++) {
        float gv = g[c];
        for (int j = 0; j < 10; j++) lg[j] += gv * Wd[c * 10 + j];
    }
    float m = lg[0];
    for (int j = 1; j < 10; j++) m = fmaxf(m, lg[j]);
    float e[10], s = 0.0f;
    for (int j = 0; j < 10; j++) { e[j] = expf(lg[j] - m); s += e[j]; }
    float invs = 1.0f / s;
    int am = 0;
    float best = -1.0f;
    for (int j = 0; j < 10; j++) {
        float p = e[j] * invs;
        if (j < out_size) out[j] = p;
        if (p > best) { best = p; am = j; }
    }
    for (int i = 10; i < out_size; i++) out[i] = (float)am;
}

// ---------------- launch ------------------------------------------------------
extern "C" void kernel_launch(void* const* d_in, const int* in_sizes, int n_in,
                              void* d_out, int out_size) {
    const float* pos = (const float*)d_in[0];
    const int*   face = (const int*)d_in[1];
    const float* W1l = (const float*)d_in[2];
    const float* W1r = (const float*)d_in[3];
    const float* b1  = (const float*)d_in[4];
    const float* W2l = (const float*)d_in[5];
    const float* W2r = (const float*)d_in[6];
    const float* b2  = (const float*)d_in[7];
    const float* Wd  = (const float*)d_in[8];
    const float* bd  = (const float*)d_in[9];
    float* out = (float*)d_out;

    k_zero   <<<(NN + 1023) / 1024, 1024>>>();
    k_weights<<<(KTOT * 256 + 255) / 256, 256>>>(W2l, W2r);
    k_hist   <<<(NE + 255) / 256, 256>>>(face);
    k_scan1  <<<196, 1024>>>();
    k_scan2  <<<1, 256>>>();
    k_scan3  <<<196, 1024>>>();
    k_fill   <<<(NE + 255) / 256, 256>>>(face);
    k_layer1 <<<(NN + 7) / 8, 256>>>(pos, W1l, W1r, b1);
    k_gemm   <<<(NN + BM - 1) / BM, 512>>>();
    k_layer2 <<<1184, 256>>>(b2);
    k_final  <<<1, 32>>>(Wd, bd, out, out_size);
}

// round 2
// speedup vs baseline: 1.2580x; 1.2580x over previous
#include <cuda_runtime.h>
#include <cuda_bf16.h>
#include <cstdint>

#define NN 200000
#define NF 400000
#define NE (3*NF)

#define BM 128
#define BN 256
#define BK 32
#define KH 256     // h1 width; W2 split into hi+lo bf16 halves applied per A-tile

// ---------------- scratch (static device globals; no runtime allocation) ----
__device__ int g_deg[NN];
__device__ int g_rowptr[NN + 1];
__device__ int g_cursor[NN];
__device__ int g_bsums[256];
__device__ int g_colidx[NE];
__device__ __nv_bfloat16 g_h1[(size_t)NN * 256];   // 102.4 MB
__device__ __nv_bfloat16 g_tu[(size_t)NN * 256];   // 102.4 MB: cols 0..127 = t, 128..255 = u
__device__ __nv_bfloat16 g_Wc[512 * 256];          // rows 0-255 hi(W2l|W2r), 256-511 lo residual
__device__ float g_gsum[128];

// ---------------- K0: zero counters ----------------------------------------
__global__ void k_zero() {
    int i = blockIdx.x * blockDim.x + threadIdx.x;
    if (i < NN) g_deg[i] = 0;
    if (i < 128) g_gsum[i] = 0.0f;
}

// ---------------- Kw: build combined split-precision weight matrix ---------
__global__ void k_weights(const float* __restrict__ W2l, const float* __restrict__ W2r) {
    int idx = blockIdx.x * blockDim.x + threadIdx.x;
    if (idx >= 512 * 256) return;
    int k = idx >> 8, c = idx & 255;
    int ks = k & 255;
    float w = (c < 128) ? W2l[ks * 128 + c] : W2r[ks * 128 + (c - 128)];
    __nv_bfloat16 hi = __float2bfloat16(w);
    if (k < 256) g_Wc[idx] = hi;
    else         g_Wc[idx] = __float2bfloat16(w - __bfloat162float(hi));
}

// ---------------- edge decode helper ----------------------------------------
__device__ __forceinline__ void edge_decode(const int* __restrict__ face, int e,
                                            int& src, int& dst) {
    int t = e / NF;
    int f = e - t * NF;
    if (t == 0)      { src = face[f];          dst = face[NF + f];     }
    else if (t == 1) { src = face[NF + f];     dst = face[2 * NF + f]; }
    else             { src = face[f];          dst = face[2 * NF + f]; }
}

// ---------------- K1: degree histogram --------------------------------------
__global__ void k_hist(const int* __restrict__ face) {
    int e = blockIdx.x * blockDim.x + threadIdx.x;
    if (e >= NE) return;
    int src, dst;
    edge_decode(face, e, src, dst);
    if (src != dst) atomicAdd(&g_deg[dst], 1);
}

// ---------------- scan (3 kernels) ------------------------------------------
__global__ void k_scan1() {
    __shared__ int s[1024];
    int i = blockIdx.x * 1024 + threadIdx.x;
    int v = (i < NN) ? g_deg[i] : 0;
    s[threadIdx.x] = v;
    __syncthreads();
    #pragma unroll
    for (int off = 1; off < 1024; off <<= 1) {
        int t = (threadIdx.x >= off) ? s[threadIdx.x - off] : 0;
        __syncthreads();
        s[threadIdx.x] += t;
        __syncthreads();
    }
    if (i < NN) g_rowptr[i] = s[threadIdx.x] - v;   // exclusive (local)
    if (threadIdx.x == 1023) g_bsums[blockIdx.x] = s[1023];
}

__global__ void k_scan2() {
    __shared__ int s[256];
    int v = (threadIdx.x < 196) ? g_bsums[threadIdx.x] : 0;
    s[threadIdx.x] = v;
    __syncthreads();
    #pragma unroll
    for (int off = 1; off < 256; off <<= 1) {
        int t = (threadIdx.x >= off) ? s[threadIdx.x - off] : 0;
        __syncthreads();
        s[threadIdx.x] += t;
        __syncthreads();
    }
    g_bsums[threadIdx.x] = s[threadIdx.x] - v;      // exclusive block offsets
    if (threadIdx.x == 255) g_rowptr[NN] = s[255];  // total valid edges
}

__global__ void k_scan3() {
    int i = blockIdx.x * 1024 + threadIdx.x;
    if (i < NN) {
        int r = g_rowptr[i] + g_bsums[i >> 10];
        g_rowptr[i] = r;
        g_cursor[i] = r;
    }
}

// ---------------- Kf: fill CSR column indices --------------------------------
__global__ void k_fill(const int* __restrict__ face) {
    int e = blockIdx.x * blockDim.x + threadIdx.x;
    if (e >= NE) return;
    int src, dst;
    edge_decode(face, e, src, dst);
    if (src != dst) {
        int p = atomicAdd(&g_cursor[dst], 1);
        g_colidx[p] = src;
    }
}

// ---------------- KA: fused layer-1 (agg + dense + relu) -> h1 bf16 ----------
__global__ void k_layer1(const float* __restrict__ pos, const float* __restrict__ W1l,
                         const float* __restrict__ W1r, const float* __restrict__ b1) {
    __shared__ float sw[1792];  // [0..767] W1l, [768..1535] W1r, [1536..1791] b1
    for (int i = threadIdx.x; i < 1792; i += blockDim.x)
        sw[i] = (i < 768) ? W1l[i] : (i < 1536 ? W1r[i - 768] : b1[i - 1536]);
    __syncthreads();
    const float* wl = sw;
    const float* wr = sw + 768;
    const float* bb = sw + 1536;

    int wid = threadIdx.x >> 5, lane = threadIdx.x & 31;
    int node = blockIdx.x * (blockDim.x >> 5) + wid;
    if (node >= NN) return;

    int beg = g_rowptr[node], end = g_rowptr[node + 1];
    float ax = 0.f, ay = 0.f, az = 0.f;
    for (int j = beg + lane; j < end; j += 32) {
        int s = g_colidx[j];
        ax += pos[3 * s + 0];
        ay += pos[3 * s + 1];
        az += pos[3 * s + 2];
    }
    #pragma unroll
    for (int off = 16; off; off >>= 1) {
        ax += __shfl_down_sync(0xffffffffu, ax, off);
        ay += __shfl_down_sync(0xffffffffu, ay, off);
        az += __shfl_down_sync(0xffffffffu, az, off);
    }
    float inv = 1.0f / fmaxf((float)(end - beg), 1.0f);
    ax = __shfl_sync(0xffffffffu, ax, 0) * inv;
    ay = __shfl_sync(0xffffffffu, ay, 0) * inv;
    az = __shfl_sync(0xffffffffu, az, 0) * inv;

    float px = pos[3 * node + 0], py = pos[3 * node + 1], pz = pos[3 * node + 2];

    int c0 = lane * 8;
    uint4 outv;
    unsigned* po = (unsigned*)&outv;
    #pragma unroll
    for (int t = 0; t < 4; t++) {
        int c = c0 + 2 * t;
        float h0 = bb[c] + ax * wl[c] + ay * wl[256 + c] + az * wl[512 + c]
                         + px * wr[c] + py * wr[256 + c] + pz * wr[512 + c];
        int c1 = c + 1;
        float h1v = bb[c1] + ax * wl[c1] + ay * wl[256 + c1] + az * wl[512 + c1]
                           + px * wr[c1] + py * wr[256 + c1] + pz * wr[512 + c1];
        h0 = fmaxf(h0, 0.0f);
        h1v = fmaxf(h1v, 0.0f);
        __nv_bfloat162 p2 = __floats2bfloat162_rn(h0, h1v);
        po[t] = *(unsigned*)&p2;
    }
    ((uint4*)(g_h1 + (size_t)node * 256))[lane] = outv;
}

// ---------------- KG: bf16 mma GEMM  tu = h1 @ Whi + h1 @ Wlo (one A pass) ---
__global__ void __launch_bounds__(512, 1) k_gemm() {
    __shared__ __nv_bfloat16 As[BM][BK + 24];   // stride 56 elems = 112B
    __shared__ __nv_bfloat16 Bh[BK][BN + 8];    // hi weights tile
    __shared__ __nv_bfloat16 Bl[BK][BN + 8];    // lo residual tile

    int tid = threadIdx.x;
    int warp = tid >> 5, lane = tid & 31;
    int wm = warp & 3, wn = warp >> 2;          // 4 (M) x 4 (N) warps; warp tile 32x64
    int bm = blockIdx.x * BM;

    float c[2][8][4];
    #pragma unroll
    for (int mi = 0; mi < 2; mi++)
        #pragma unroll
        for (int ni = 0; ni < 8; ni++)
            #pragma unroll
            for (int q = 0; q < 4; q++) c[mi][ni][q] = 0.0f;

    for (int k0 = 0; k0 < KH; k0 += BK) {
        // load A tile: 128 x 32 bf16 (single pass over h1)
        {
            int row = tid >> 2, cq = tid & 3;
            int node = bm + row;
            uint4 val = make_uint4(0, 0, 0, 0);
            if (node < NN) val = *(const uint4*)(g_h1 + (size_t)node * 256 + k0 + cq * 8);
            *(uint4*)(&As[row][cq * 8]) = val;
        }
        // load B tiles (hi rows k0.., lo rows 256+k0..): 32 x 256 each
        #pragma unroll
        for (int r = 0; r < 2; r++) {
            int u = tid + 512 * r;
            int row = u >> 5, cq = u & 31;
            *(uint4*)(&Bh[row][cq * 8]) =
                *(const uint4*)(g_Wc + (size_t)(k0 + row) * 256 + cq * 8);
            *(uint4*)(&Bl[row][cq * 8]) =
                *(const uint4*)(g_Wc + (size_t)(256 + k0 + row) * 256 + cq * 8);
        }
        __syncthreads();

        #pragma unroll
        for (int kk = 0; kk < BK; kk += 16) {
            uint32_t a[2][4];
            #pragma unroll
            for (int mi = 0; mi < 2; mi++) {
                int r = wm * 32 + mi * 16 + (lane & 7) + 8 * ((lane >> 3) & 1);
                int cc = kk + 8 * (lane >> 4);
                uint32_t addr = (uint32_t)__cvta_generic_to_shared(&As[r][cc]);
                asm volatile("ldmatrix.sync.aligned.m8n8.x4.shared.b16 {%0,%1,%2,%3}, [%4];"
                             : "=r"(a[mi][0]), "=r"(a[mi][1]), "=r"(a[mi][2]), "=r"(a[mi][3])
                             : "r"(addr));
            }
            int rr = kk + (lane & 7) + 8 * ((lane >> 3) & 1);
            #pragma unroll
            for (int np = 0; np < 4; np++) {
                int ncol = wn * 64 + np * 16 + 8 * (lane >> 4);
                uint32_t bh[4], bl[4];
                uint32_t bha = (uint32_t)__cvta_generic_to_shared(&Bh[rr][ncol]);
                asm volatile("ldmatrix.sync.aligned.m8n8.x4.trans.shared.b16 {%0,%1,%2,%3}, [%4];"
                             : "=r"(bh[0]), "=r"(bh[1]), "=r"(bh[2]), "=r"(bh[3])
                             : "r"(bha));
                uint32_t bla = (uint32_t)__cvta_generic_to_shared(&Bl[rr][ncol]);
                asm volatile("ldmatrix.sync.aligned.m8n8.x4.trans.shared.b16 {%0,%1,%2,%3}, [%4];"
                             : "=r"(bl[0]), "=r"(bl[1]), "=r"(bl[2]), "=r"(bl[3])
                             : "r"(bla));
                #pragma unroll
                for (int mi = 0; mi < 2; mi++) {
                    #pragma unroll
                    for (int h = 0; h < 2; h++) {
                        int ni = np * 2 + h;
                        asm volatile(
                            "mma.sync.aligned.m16n8k16.row.col.f32.bf16.bf16.f32 "
                            "{%0,%1,%2,%3},{%4,%5,%6,%7},{%8,%9},{%0,%1,%2,%3};"
                            : "+f"(c[mi][ni][0]), "+f"(c[mi][ni][1]),
                              "+f"(c[mi][ni][2]), "+f"(c[mi][ni][3])
                            : "r"(a[mi][0]), "r"(a[mi][1]), "r"(a[mi][2]), "r"(a[mi][3]),
                              "r"(bh[2 * h]), "r"(bh[2 * h + 1]));
                        asm volatile(
                            "mma.sync.aligned.m16n8k16.row.col.f32.bf16.bf16.f32 "
                            "{%0,%1,%2,%3},{%4,%5,%6,%7},{%8,%9},{%0,%1,%2,%3};"
                            : "+f"(c[mi][ni][0]), "+f"(c[mi][ni][1]),
                              "+f"(c[mi][ni][2]), "+f"(c[mi][ni][3])
                            : "r"(a[mi][0]), "r"(a[mi][1]), "r"(a[mi][2]), "r"(a[mi][3]),
                              "r"(bl[2 * h]), "r"(bl[2 * h + 1]));
                    }
                }
            }
        }
        __syncthreads();
    }

    // epilogue: bf16 store to g_tu
    int gid = lane >> 2, qid = lane & 3;
    #pragma unroll
    for (int mi = 0; mi < 2; mi++) {
        int r0 = bm + wm * 32 + mi * 16 + gid;
        int r1 = r0 + 8;
        #pragma unroll
        for (int ni = 0; ni < 8; ni++) {
            int col = wn * 64 + ni * 8 + qid * 2;
            if (r0 < NN) {
                __nv_bfloat162 p = __floats2bfloat162_rn(c[mi][ni][0], c[mi][ni][1]);
                *(unsigned*)(g_tu + (size_t)r0 * 256 + col) = *(unsigned*)&p;
            }
            if (r1 < NN) {
                __nv_bfloat162 p = __floats2bfloat162_rn(c[mi][ni][2], c[mi][ni][3]);
                *(unsigned*)(g_tu + (size_t)r1 * 256 + col) = *(unsigned*)&p;
            }
        }
    }
}

// ---------------- KB: fused layer-2 aggregate + relu + global mean partials --
__global__ void k_layer2(const float* __restrict__ b2) {
    __shared__ float gsh[128];
    if (threadIdx.x < 128) gsh[threadIdx.x] = 0.0f;
    __syncthreads();

    int wid = threadIdx.x >> 5, lane = threadIdx.x & 31;
    int gwarp = blockIdx.x * (blockDim.x >> 5) + wid;
    int nwarps = gridDim.x * (blockDim.x >> 5);
    float4 bl = ((const float4*)b2)[lane];   // channels lane*4 .. lane*4+3

    float a0 = 0.f, a1 = 0.f, a2 = 0.f, a3 = 0.f;
    for (int node = gwarp; node < NN; node += nwarps) {
        int beg = g_rowptr[node], end = g_rowptr[node + 1];
        float s0 = 0.f, s1 = 0.f, s2 = 0.f, s3 = 0.f;
        for (int j = beg; j < end; j++) {
            int src = g_colidx[j];
            uint2 tv = ((const uint2*)(g_tu + (size_t)src * 256))[lane];
            __nv_bfloat162 t01 = *(__nv_bfloat162*)&tv.x;
            __nv_bfloat162 t23 = *(__nv_bfloat162*)&tv.y;
            s0 += __bfloat162float(t01.x); s1 += __bfloat162float(t01.y);
            s2 += __bfloat162float(t23.x); s3 += __bfloat162float(t23.y);
        }
        float inv = 1.0f / fmaxf((float)(end - beg), 1.0f);
        uint2 uv = ((const uint2*)(g_tu + (size_t)node * 256 + 128))[lane];
        __nv_bfloat162 u01 = *(__nv_bfloat162*)&uv.x;
        __nv_bfloat162 u23 = *(__nv_bfloat162*)&uv.y;
        a0 += fmaxf(s0 * inv + __bfloat162float(u01.x) + bl.x, 0.0f);
        a1 += fmaxf(s1 * inv + __bfloat162float(u01.y) + bl.y, 0.0f);
        a2 += fmaxf(s2 * inv + __bfloat162float(u23.x) + bl.z, 0.0f);
        a3 += fmaxf(s3 * inv + __bfloat162float(u23.y) + bl.w, 0.0f);
    }
    atomicAdd(&gsh[lane * 4 + 0], a0);
    atomicAdd(&gsh[lane * 4 + 1], a1);
    atomicAdd(&gsh[lane * 4 + 2], a2);
    atomicAdd(&gsh[lane * 4 + 3], a3);
    __syncthreads();
    if (threadIdx.x < 128) atomicAdd(&g_gsum[threadIdx.x], gsh[threadIdx.x]);
}

// ---------------- KC: decoder + softmax + argmax -----------------------------
__global__ void k_final(const float* __restrict__ Wd, const float* __restrict__ bd,
                        float* __restrict__ out, int out_size) {
    if (threadIdx.x != 0 || blockIdx.x != 0) return;
    float g[128];
    for (int c = 0; c < 128; c++) g[c] = g_gsum[c] * (1.0f / (float)NN);
    float lg[10];
    for (int j = 0; j < 10; j++) lg[j] = bd[j];
    for (int c = 0; c < 128; c++) {
        float gv = g[c];
        for (int j = 0; j < 10; j++) lg[j] += gv * Wd[c * 10 + j];
    }
    float m = lg[0];
    for (int j = 1; j < 10; j++) m = fmaxf(m, lg[j]);
    float e[10], s = 0.0f;
    for (int j = 0; j < 10; j++) { e[j] = expf(lg[j] - m); s += e[j]; }
    float invs = 1.0f / s;
    int am = 0;
    float best = -1.0f;
    for (int j = 0; j < 10; j++) {
        float p = e[j] * invs;
        if (j < out_size) out[j] = p;
        if (p > best) { best = p; am = j; }
    }
    for (int i = 10; i < out_size; i++) out[i] = (float)am;
}

// ---------------- launch ------------------------------------------------------
extern "C" void kernel_launch(void* const* d_in, const int* in_sizes, int n_in,
                              void* d_out, int out_size) {
    const float* pos = (const float*)d_in[0];
    const int*   face = (const int*)d_in[1];
    const float* W1l = (const float*)d_in[2];
    const float* W1r = (const float*)d_in[3];
    const float* b1  = (const float*)d_in[4];
    const float* W2l = (const float*)d_in[5];
    const float* W2r = (const float*)d_in[6];
    const float* b2  = (const float*)d_in[7];
    const float* Wd  = (const float*)d_in[8];
    const float* bd  = (const float*)d_in[9];
    float* out = (float*)d_out;

    k_zero   <<<(NN + 1023) / 1024, 1024>>>();
    k_weights<<<(512 * 256 + 255) / 256, 256>>>(W2l, W2r);
    k_hist   <<<(NE + 255) / 256, 256>>>(face);
    k_scan1  <<<196, 1024>>>();
    k_scan2  <<<1, 256>>>();
    k_scan3  <<<196, 1024>>>();
    k_fill   <<<(NE + 255) / 256, 256>>>(face);
    k_layer1 <<<(NN + 7) / 8, 256>>>(pos, W1l, W1r, b1);
    k_gemm   <<<(NN + BM - 1) / BM, 512>>>();
    k_layer2 <<<1184, 256>>>(b2);
    k_final  <<<1, 32>>>(Wd, bd, out, out_size);
}

// round 4
// speedup vs baseline: 1.2671x; 1.0073x over previous
#include <cuda_runtime.h>
#include <cuda_bf16.h>
#include <cstdint>

#define NN 200000
#define NF 400000
#define NE (3*NF)

#define BM 128
#define BN 256
#define BK 32
#define KH 256     // h1 width; W2 split into hi+lo bf16 applied per A-tile

// ---------------- scratch (static device globals) ---------------------------
__device__ int g_deg[NN];
__device__ int g_rowptr[NN + 1];
__device__ int g_cursor[NN];
__device__ int g_bsums[256];
__device__ int g_colidx[NE];
__device__ __nv_bfloat16 g_h1[(size_t)NN * 256];   // 102.4 MB
__device__ __nv_bfloat16 g_t[(size_t)NN * 128];    // 51.2 MB (gathered -> L2 resident)
__device__ __nv_bfloat16 g_u[(size_t)NN * 128];    // 51.2 MB (streamed once)
__device__ __nv_bfloat16 g_Wc[512 * 256];          // rows 0-255 hi(W2l|W2r), 256-511 lo residual
__device__ float g_gsum[128];

// ---------------- K0: zero counters ----------------------------------------
__global__ void k_zero() {
    int i = blockIdx.x * blockDim.x + threadIdx.x;
    if (i < NN) g_deg[i] = 0;
    if (i < 128) g_gsum[i] = 0.0f;
}

// ---------------- Kw: combined split-precision weights ----------------------
__global__ void k_weights(const float* __restrict__ W2l, const float* __restrict__ W2r) {
    int idx = blockIdx.x * blockDim.x + threadIdx.x;
    if (idx >= 512 * 256) return;
    int k = idx >> 8, c = idx & 255;
    int ks = k & 255;
    float w = (c < 128) ? W2l[ks * 128 + c] : W2r[ks * 128 + (c - 128)];
    __nv_bfloat16 hi = __float2bfloat16(w);
    if (k < 256) g_Wc[idx] = hi;
    else         g_Wc[idx] = __float2bfloat16(w - __bfloat162float(hi));
}

// ---------------- edge decode ------------------------------------------------
__device__ __forceinline__ void edge_decode(const int* __restrict__ face, int e,
                                            int& src, int& dst) {
    int t = e / NF;
    int f = e - t * NF;
    if (t == 0)      { src = face[f];          dst = face[NF + f];     }
    else if (t == 1) { src = face[NF + f];     dst = face[2 * NF + f]; }
    else             { src = face[f];          dst = face[2 * NF + f]; }
}

// ---------------- K1: degree histogram ---------------------------------------
__global__ void k_hist(const int* __restrict__ face) {
    int e = blockIdx.x * blockDim.x + threadIdx.x;
    if (e >= NE) return;
    int src, dst;
    edge_decode(face, e, src, dst);
    if (src != dst) atomicAdd(&g_deg[dst], 1);
}

// ---------------- scan (3 kernels) --------------------------------------------
__global__ void k_scan1() {
    __shared__ int s[1024];
    int i = blockIdx.x * 1024 + threadIdx.x;
    int v = (i < NN) ? g_deg[i] : 0;
    s[threadIdx.x] = v;
    __syncthreads();
    #pragma unroll
    for (int off = 1; off < 1024; off <<= 1) {
        int t = (threadIdx.x >= off) ? s[threadIdx.x - off] : 0;
        __syncthreads();
        s[threadIdx.x] += t;
        __syncthreads();
    }
    if (i < NN) g_rowptr[i] = s[threadIdx.x] - v;
    if (threadIdx.x == 1023) g_bsums[blockIdx.x] = s[1023];
}

__global__ void k_scan2() {
    __shared__ int s[256];
    int v = (threadIdx.x < 196) ? g_bsums[threadIdx.x] : 0;
    s[threadIdx.x] = v;
    __syncthreads();
    #pragma unroll
    for (int off = 1; off < 256; off <<= 1) {
        int t = (threadIdx.x >= off) ? s[threadIdx.x - off] : 0;
        __syncthreads();
        s[threadIdx.x] += t;
        __syncthreads();
    }
    g_bsums[threadIdx.x] = s[threadIdx.x] - v;
    if (threadIdx.x == 255) g_rowptr[NN] = s[255];
}

__global__ void k_scan3() {
    int i = blockIdx.x * 1024 + threadIdx.x;
    if (i < NN) {
        int r = g_rowptr[i] + g_bsums[i >> 10];
        g_rowptr[i] = r;
        g_cursor[i] = r;
    }
}

// ---------------- Kf: fill CSR -------------------------------------------------
__global__ void k_fill(const int* __restrict__ face) {
    int e = blockIdx.x * blockDim.x + threadIdx.x;
    if (e >= NE) return;
    int src, dst;
    edge_decode(face, e, src, dst);
    if (src != dst) {
        int p = atomicAdd(&g_cursor[dst], 1);
        g_colidx[p] = src;
    }
}

// ---------------- KA: fused layer-1 -> h1 bf16 ---------------------------------
__global__ void k_layer1(const float* __restrict__ pos, const float* __restrict__ W1l,
                         const float* __restrict__ W1r, const float* __restrict__ b1) {
    __shared__ float sw[1792];
    for (int i = threadIdx.x; i < 1792; i += blockDim.x)
        sw[i] = (i < 768) ? W1l[i] : (i < 1536 ? W1r[i - 768] : b1[i - 1536]);
    __syncthreads();
    const float* wl = sw;
    const float* wr = sw + 768;
    const float* bb = sw + 1536;

    int wid = threadIdx.x >> 5, lane = threadIdx.x & 31;
    int node = blockIdx.x * (blockDim.x >> 5) + wid;
    if (node >= NN) return;

    int beg = g_rowptr[node], end = g_rowptr[node + 1];
    float ax = 0.f, ay = 0.f, az = 0.f;
    for (int j = beg + lane; j < end; j += 32) {
        int s = g_colidx[j];
        ax += pos[3 * s + 0];
        ay += pos[3 * s + 1];
        az += pos[3 * s + 2];
    }
    #pragma unroll
    for (int off = 16; off; off >>= 1) {
        ax += __shfl_down_sync(0xffffffffu, ax, off);
        ay += __shfl_down_sync(0xffffffffu, ay, off);
        az += __shfl_down_sync(0xffffffffu, az, off);
    }
    float inv = 1.0f / fmaxf((float)(end - beg), 1.0f);
    ax = __shfl_sync(0xffffffffu, ax, 0) * inv;
    ay = __shfl_sync(0xffffffffu, ay, 0) * inv;
    az = __shfl_sync(0xffffffffu, az, 0) * inv;

    float px = pos[3 * node + 0], py = pos[3 * node + 1], pz = pos[3 * node + 2];

    int c0 = lane * 8;
    uint4 outv;
    unsigned* po = (unsigned*)&outv;
    #pragma unroll
    for (int t = 0; t < 4; t++) {
        int c = c0 + 2 * t;
        float h0 = bb[c] + ax * wl[c] + ay * wl[256 + c] + az * wl[512 + c]
                         + px * wr[c] + py * wr[256 + c] + pz * wr[512 + c];
        int c1 = c + 1;
        float h1v = bb[c1] + ax * wl[c1] + ay * wl[256 + c1] + az * wl[512 + c1]
                           + px * wr[c1] + py * wr[256 + c1] + pz * wr[512 + c1];
        h0 = fmaxf(h0, 0.0f);
        h1v = fmaxf(h1v, 0.0f);
        __nv_bfloat162 p2 = __floats2bfloat162_rn(h0, h1v);
        po[t] = *(unsigned*)&p2;
    }
    ((uint4*)(g_h1 + (size_t)node * 256))[lane] = outv;
}

// ---------------- KG: bf16 mma GEMM  [t|u] = h1 @ (Whi + Wlo), one A pass -----
__global__ void __launch_bounds__(512, 1) k_gemm() {
    __shared__ __nv_bfloat16 As[BM][BK + 24];   // stride 56 elems = 112B
    __shared__ __nv_bfloat16 Bh[BK][BN + 8];    // hi weights tile
    __shared__ __nv_bfloat16 Bl[BK][BN + 8];    // lo residual tile

    int tid = threadIdx.x;
    int warp = tid >> 5, lane = tid & 31;
    int wm = warp & 3, wn = warp >> 2;          // 4 (M) x 4 (N) warps; warp tile 32x64
    int bm = blockIdx.x * BM;

    float c[2][8][4];
    #pragma unroll
    for (int mi = 0; mi < 2; mi++)
        #pragma unroll
        for (int ni = 0; ni < 8; ni++)
            #pragma unroll
            for (int q = 0; q < 4; q++) c[mi][ni][q] = 0.0f;

    for (int k0 = 0; k0 < KH; k0 += BK) {
        {
            int row = tid >> 2, cq = tid & 3;
            int node = bm + row;
            uint4 val = make_uint4(0, 0, 0, 0);
            if (node < NN) val = *(const uint4*)(g_h1 + (size_t)node * 256 + k0 + cq * 8);
            *(uint4*)(&As[row][cq * 8]) = val;
        }
        #pragma unroll
        for (int r = 0; r < 2; r++) {
            int u = tid + 512 * r;
            int row = u >> 5, cq = u & 31;
            *(uint4*)(&Bh[row][cq * 8]) =
                *(const uint4*)(g_Wc + (size_t)(k0 + row) * 256 + cq * 8);
            *(uint4*)(&Bl[row][cq * 8]) =
                *(const uint4*)(g_Wc + (size_t)(256 + k0 + row) * 256 + cq * 8);
        }
        __syncthreads();

        #pragma unroll
        for (int kk = 0; kk < BK; kk += 16) {
            uint32_t a[2][4];
            #pragma unroll
            for (int mi = 0; mi < 2; mi++) {
                int r = wm * 32 + mi * 16 + (lane & 7) + 8 * ((lane >> 3) & 1);
                int cc = kk + 8 * (lane >> 4);
                uint32_t addr = (uint32_t)__cvta_generic_to_shared(&As[r][cc]);
                asm volatile("ldmatrix.sync.aligned.m8n8.x4.shared.b16 {%0,%1,%2,%3}, [%4];"
                             : "=r"(a[mi][0]), "=r"(a[mi][1]), "=r"(a[mi][2]), "=r"(a[mi][3])
                             : "r"(addr));
            }
            int rr = kk + (lane & 7) + 8 * ((lane >> 3) & 1);
            #pragma unroll
            for (int np = 0; np < 4; np++) {
                int ncol = wn * 64 + np * 16 + 8 * (lane >> 4);
                uint32_t bh[4], bl[4];
                uint32_t bha = (uint32_t)__cvta_generic_to_shared(&Bh[rr][ncol]);
                asm volatile("ldmatrix.sync.aligned.m8n8.x4.trans.shared.b16 {%0,%1,%2,%3}, [%4];"
                             : "=r"(bh[0]), "=r"(bh[1]), "=r"(bh[2]), "=r"(bh[3])
                             : "r"(bha));
                uint32_t bla = (uint32_t)__cvta_generic_to_shared(&Bl[rr][ncol]);
                asm volatile("ldmatrix.sync.aligned.m8n8.x4.trans.shared.b16 {%0,%1,%2,%3}, [%4];"
                             : "=r"(bl[0]), "=r"(bl[1]), "=r"(bl[2]), "=r"(bl[3])
                             : "r"(bla));
                #pragma unroll
                for (int mi = 0; mi < 2; mi++) {
                    #pragma unroll
                    for (int h = 0; h < 2; h++) {
                        int ni = np * 2 + h;
                        asm volatile(
                            "mma.sync.aligned.m16n8k16.row.col.f32.bf16.bf16.f32 "
                            "{%0,%1,%2,%3},{%4,%5,%6,%7},{%8,%9},{%0,%1,%2,%3};"
                            : "+f"(c[mi][ni][0]), "+f"(c[mi][ni][1]),
                              "+f"(c[mi][ni][2]), "+f"(c[mi][ni][3])
                            : "r"(a[mi][0]), "r"(a[mi][1]), "r"(a[mi][2]), "r"(a[mi][3]),
                              "r"(bh[2 * h]), "r"(bh[2 * h + 1]));
                        asm volatile(
                            "mma.sync.aligned.m16n8k16.row.col.f32.bf16.bf16.f32 "
                            "{%0,%1,%2,%3},{%4,%5,%6,%7},{%8,%9},{%0,%1,%2,%3};"
                            : "+f"(c[mi][ni][0]), "+f"(c[mi][ni][1]),
                              "+f"(c[mi][ni][2]), "+f"(c[mi][ni][3])
                            : "r"(a[mi][0]), "r"(a[mi][1]), "r"(a[mi][2]), "r"(a[mi][3]),
                              "r"(bl[2 * h]), "r"(bl[2 * h + 1]));
                    }
                }
            }
        }
        __syncthreads();
    }

    // epilogue: bf16 store, cols <128 -> g_t, cols >=128 -> g_u
    int gid = lane >> 2, qid = lane & 3;
    #pragma unroll
    for (int mi = 0; mi < 2; mi++) {
        int r0 = bm + wm * 32 + mi * 16 + gid;
        int r1 = r0 + 8;
        #pragma unroll
        for (int ni = 0; ni < 8; ni++) {
            int col = wn * 64 + ni * 8 + qid * 2;
            __nv_bfloat16* base0;
            int cc;
            if (col < 128) { base0 = g_t; cc = col; }
            else           { base0 = g_u; cc = col - 128; }
            if (r0 < NN) {
                __nv_bfloat162 p = __floats2bfloat162_rn(c[mi][ni][0], c[mi][ni][1]);
                *(unsigned*)(base0 + (size_t)r0 * 128 + cc) = *(unsigned*)&p;
            }
            if (r1 < NN) {
                __nv_bfloat162 p = __floats2bfloat162_rn(c[mi][ni][2], c[mi][ni][3]);
                *(unsigned*)(base0 + (size_t)r1 * 128 + cc) = *(unsigned*)&p;
            }
        }
    }
}

// ---------------- KB: fused layer-2 aggregate + relu + mean-pool --------------
__global__ void k_layer2(const float* __restrict__ b2) {
    __shared__ float gsh[128];
    if (threadIdx.x < 128) gsh[threadIdx.x] = 0.0f;
    __syncthreads();

    int wid = threadIdx.x >> 5, lane = threadIdx.x & 31;
    int gwarp = blockIdx.x * (blockDim.x >> 5) + wid;
    int nwarps = gridDim.x * (blockDim.x >> 5);
    float4 bl = ((const float4*)b2)[lane];

    float a0 = 0.f, a1 = 0.f, a2 = 0.f, a3 = 0.f;
    for (int node = gwarp; node < NN; node += nwarps) {
        int beg = g_rowptr[node], end = g_rowptr[node + 1];
        float s0 = 0.f, s1 = 0.f, s2 = 0.f, s3 = 0.f;
        for (int j = beg; j < end; j++) {
            int src = g_colidx[j];
            uint2 tv = ((const uint2*)(g_t + (size_t)src * 128))[lane];
            __nv_bfloat162 t01 = *(__nv_bfloat162*)&tv.x;
            __nv_bfloat162 t23 = *(__nv_bfloat162*)&tv.y;
            s0 += __bfloat162float(t01.x); s1 += __bfloat162float(t01.y);
            s2 += __bfloat162float(t23.x); s3 += __bfloat162float(t23.y);
        }
        float inv = 1.0f / fmaxf((float)(end - beg), 1.0f);
        uint2 uv = ((const uint2*)(g_u + (size_t)node * 128))[lane];
        __nv_bfloat162 u01 = *(__nv_bfloat162*)&uv.x;
        __nv_bfloat162 u23 = *(__nv_bfloat162*)&uv.y;
        a0 += fmaxf(s0 * inv + __bfloat162float(u01.x) + bl.x, 0.0f);
        a1 += fmaxf(s1 * inv + __bfloat162float(u01.y) + bl.y, 0.0f);
        a2 += fmaxf(s2 * inv + __bfloat162float(u23.x) + bl.z, 0.0f);
        a3 += fmaxf(s3 * inv + __bfloat162float(u23.y) + bl.w, 0.0f);
    }
    atomicAdd(&gsh[lane * 4 + 0], a0);
    atomicAdd(&gsh[lane * 4 + 1], a1);
    atomicAdd(&gsh[lane * 4 + 2], a2);
    atomicAdd(&gsh[lane * 4 + 3], a3);
    __syncthreads();
    if (threadIdx.x < 128) atomicAdd(&g_gsum[threadIdx.x], gsh[threadIdx.x]);
}

// ---------------- KC: decoder + softmax + argmax -------------------------------
__global__ void k_final(const float* __restrict__ Wd, const float* __restrict__ bd,
                        float* __restrict__ out, int out_size) {
    if (threadIdx.x != 0 || blockIdx.x != 0) return;
    float g[128];
    for (int c = 0; c < 128; c++) g[c] = g_gsum[c] * (1.0f / (float)NN);
    float lg[10];
    for (int j = 0; j < 10; j++) lg[j] = bd[j];
    for (int c = 0; c < 128; c++) {
        float gv = g[c];
        for (int j = 0; j < 10; j++) lg[j] += gv * Wd[c * 10 + j];
    }
    float m = lg[0];
    for (int j = 1; j < 10; j++) m = fmaxf(m, lg[j]);
    float e[10], s = 0.0f;
    for (int j = 0; j < 10; j++) { e[j] = expf(lg[j] - m); s += e[j]; }
    float invs = 1.0f / s;
    int am = 0;
    float best = -1.0f;
    for (int j = 0; j < 10; j++) {
        float p = e[j] * invs;
        if (j < out_size) out[j] = p;
        if (p > best) { best = p; am = j; }
    }
    for (int i = 10; i < out_size; i++) out[i] = (float)am;
}

// ---------------- launch --------------------------------------------------------
extern "C" void kernel_launch(void* const* d_in, const int* in_sizes, int n_in,
                              void* d_out, int out_size) {
    const float* pos = (const float*)d_in[0];
    const int*   face = (const int*)d_in[1];
    const float* W1l = (const float*)d_in[2];
    const float* W1r = (const float*)d_in[3];
    const float* b1  = (const float*)d_in[4];
    const float* W2l = (const float*)d_in[5];
    const float* W2r = (const float*)d_in[6];
    const float* b2  = (const float*)d_in[7];
    const float* Wd  = (const float*)d_in[8];
    const float* bd  = (const float*)d_in[9];
    float* out = (float*)d_out;

    k_zero   <<<(NN + 1023) / 1024, 1024>>>();
    k_weights<<<(512 * 256 + 255) / 256, 256>>>(W2l, W2r);
    k_hist   <<<(NE + 255) / 256, 256>>>(face);
    k_scan1  <<<196, 1024>>>();
    k_scan2  <<<1, 256>>>();
    k_scan3  <<<196, 1024>>>();
    k_fill   <<<(NE + 255) / 256, 256>>>(face);
    k_layer1 <<<(NN + 7) / 8, 256>>>(pos, W1l, W1r, b1);
    k_gemm   <<<(NN + BM - 1) / BM, 512>>>();
    k_layer2 <<<1184, 256>>>(b2);
    k_final  <<<1, 32>>>(Wd, bd, out, out_size);
}